// round 2
// baseline (speedup 1.0000x reference)
#include <cuda_runtime.h>
#include <math.h>

#define B_ 256
#define Q_ 128
#define P_ 16
#define D_ 256
#define H_ 16
#define F_ 512
#define DK_ 16
#define MROWS (B_*Q_)        // 32768
#define SCALE_ 0.25f         // DK^-0.5
#define EPS_ 1e-5f

// ---- scratch (device globals: allocation-free) ----
__device__ float g_z [MROWS*D_];
__device__ float g_q [MROWS*D_];
__device__ float g_k [MROWS*D_];
__device__ float g_v [MROWS*D_];
__device__ float g_o [MROWS*D_];
__device__ float g_t [MROWS*D_];
__device__ float g_f [MROWS*F_];
__device__ float g_sc[(size_t)B_*H_*Q_*Q_];   // 256 MB score carry

// ---------------- embed: z = x @ W_P + b_P + W_pos ----------------
__global__ void embed_kernel(const float* __restrict__ x,
                             const float* __restrict__ W_P,
                             const float* __restrict__ b_P,
                             const float* __restrict__ W_pos) {
    int row = blockIdx.x;          // 0..32767  (b*Q + q)
    int d   = threadIdx.x;         // 0..255
    int q   = row % Q_;
    __shared__ float xs[P_];
    if (threadIdx.x < P_) xs[threadIdx.x] = x[row*P_ + threadIdx.x];
    __syncthreads();
    float acc = b_P[d] + W_pos[q*D_ + d];
#pragma unroll
    for (int p = 0; p < P_; ++p) acc += xs[p] * W_P[p*D_ + d];
    g_z[(size_t)row*D_ + d] = acc;
}

// ---------------- tiled SGEMM: C = act(A[MxK] @ W[KxN] + bias) ----------------
// 64x64 tile, BK=16, 256 threads, 4x4 per thread. M%64==0, N%64==0, K%16==0.
template<int ACT>
__global__ void gemm_kernel(const float* __restrict__ A,
                            const float* __restrict__ W,
                            const float* __restrict__ bias,
                            float* __restrict__ C,
                            int M, int N, int K) {
    __shared__ float As[16][68];   // padded, k-major
    __shared__ float Bs[16][64];
    const int tid = threadIdx.x;
    const int m0 = blockIdx.y * 64, n0 = blockIdx.x * 64;
    const int aRow = tid >> 2, aK4 = (tid & 3) << 2;
    const int bRow = tid >> 4, bN4 = (tid & 15) << 2;
    const int tx = tid & 15, ty = tid >> 4;

    float acc[4][4] = {};
    for (int k0 = 0; k0 < K; k0 += 16) {
        float4 a4 = *reinterpret_cast<const float4*>(&A[(size_t)(m0+aRow)*K + k0 + aK4]);
        float4 b4 = *reinterpret_cast<const float4*>(&W[(size_t)(k0+bRow)*N + n0 + bN4]);
        __syncthreads();
        As[aK4+0][aRow] = a4.x; As[aK4+1][aRow] = a4.y;
        As[aK4+2][aRow] = a4.z; As[aK4+3][aRow] = a4.w;
        *reinterpret_cast<float4*>(&Bs[bRow][bN4]) = b4;
        __syncthreads();
#pragma unroll
        for (int k = 0; k < 16; ++k) {
            float4 av = *reinterpret_cast<const float4*>(&As[k][ty*4]);
            float4 bv = *reinterpret_cast<const float4*>(&Bs[k][tx*4]);
            acc[0][0] += av.x*bv.x; acc[0][1] += av.x*bv.y; acc[0][2] += av.x*bv.z; acc[0][3] += av.x*bv.w;
            acc[1][0] += av.y*bv.x; acc[1][1] += av.y*bv.y; acc[1][2] += av.y*bv.z; acc[1][3] += av.y*bv.w;
            acc[2][0] += av.z*bv.x; acc[2][1] += av.z*bv.y; acc[2][2] += av.z*bv.z; acc[2][3] += av.z*bv.w;
            acc[3][0] += av.w*bv.x; acc[3][1] += av.w*bv.y; acc[3][2] += av.w*bv.z; acc[3][3] += av.w*bv.w;
        }
    }

    const int nb = n0 + tx*4;
    float4 bb = *reinterpret_cast<const float4*>(&bias[nb]);
#pragma unroll
    for (int i = 0; i < 4; ++i) {
        int m = m0 + ty*4 + i;
        float4 r;
        r.x = acc[i][0] + bb.x; r.y = acc[i][1] + bb.y;
        r.z = acc[i][2] + bb.z; r.w = acc[i][3] + bb.w;
        if (ACT == 1) {  // exact GELU
            r.x = 0.5f*r.x*(1.0f + erff(r.x*0.70710678118654752f));
            r.y = 0.5f*r.y*(1.0f + erff(r.y*0.70710678118654752f));
            r.z = 0.5f*r.z*(1.0f + erff(r.z*0.70710678118654752f));
            r.w = 0.5f*r.w*(1.0f + erff(r.w*0.70710678118654752f));
        }
        *reinterpret_cast<float4*>(&C[(size_t)m*N + nb]) = r;
    }
}

// ---------------- fused attention per (b,h) ----------------
// scores = q k^T * SCALE + prev + bias; carry update (in place); softmax; o = attn @ v
__global__ void attn_kernel(const float* __restrict__ q,
                            const float* __restrict__ k,
                            const float* __restrict__ v,
                            const float* __restrict__ bias,
                            float* __restrict__ scores,
                            float* __restrict__ o,
                            int hasPrev, int writeScores) {
    const int h = blockIdx.x, b = blockIdx.y;
    const int tid = threadIdx.x;                  // 128 threads = query rows
    extern __shared__ float sm[];
    float* ks = sm;                               // 128*16
    float* vs = sm + Q_*DK_;                      // 128*16
    float* ss = sm + 2*Q_*DK_;                    // 128*129 (padded rows)

    const size_t base = ((size_t)b*Q_)*D_ + h*DK_;
    for (int t = tid; t < Q_*DK_; t += 128) {
        int j = t >> 4, c = t & 15;
        ks[t] = k[base + (size_t)j*D_ + c];
        vs[t] = v[base + (size_t)j*D_ + c];
    }
    float qr[DK_];
#pragma unroll
    for (int c = 0; c < DK_; ++c) qr[c] = q[base + (size_t)tid*D_ + c];
    __syncthreads();

    const size_t srow = (((size_t)b*H_ + h)*Q_ + tid)*Q_;
    const float* brow = bias + (size_t)tid*Q_;
    float* my = ss + tid*(Q_+1);

    float mx = -1e30f;
    for (int j = 0; j < Q_; ++j) {
        float dot = 0.f;
#pragma unroll
        for (int c = 0; c < DK_; ++c) dot += qr[c]*ks[j*DK_ + c];
        float s = dot*SCALE_ + brow[j];
        if (hasPrev) s += scores[srow + j];
        if (writeScores) scores[srow + j] = s;
        my[j] = s;
        mx = fmaxf(mx, s);
    }
    float sum = 0.f;
    for (int j = 0; j < Q_; ++j) { float e = __expf(my[j]-mx); my[j] = e; sum += e; }
    const float inv = 1.0f/sum;

    float oa[DK_] = {};
    for (int j = 0; j < Q_; ++j) {
        float p = my[j];
#pragma unroll
        for (int c = 0; c < DK_; ++c) oa[c] += p*vs[j*DK_ + c];
    }
#pragma unroll
    for (int c = 0; c < DK_; ++c) o[base + (size_t)tid*D_ + c] = oa[c]*inv;
}

// ---------------- fused residual + LayerNorm (one block per row) ----------------
__global__ void ln_kernel(const float* __restrict__ resid,
                          const float* __restrict__ add,
                          const float* __restrict__ g,
                          const float* __restrict__ bta,
                          float* __restrict__ out) {
    const int row = blockIdx.x, d = threadIdx.x;  // 256 threads
    __shared__ float red[256];
    float val = resid[(size_t)row*D_ + d] + add[(size_t)row*D_ + d];
    red[d] = val; __syncthreads();
    for (int s = 128; s > 0; s >>= 1) { if (d < s) red[d] += red[d+s]; __syncthreads(); }
    float mu = red[0] * (1.0f/256.0f);
    __syncthreads();
    float dv = val - mu;
    red[d] = dv*dv; __syncthreads();
    for (int s = 128; s > 0; s >>= 1) { if (d < s) red[d] += red[d+s]; __syncthreads(); }
    float var = red[0] * (1.0f/256.0f);
    out[(size_t)row*D_ + d] = dv * rsqrtf(var + EPS_) * g[d] + bta[d];
}

// ---------------- launch ----------------
extern "C" void kernel_launch(void* const* d_in, const int* in_sizes, int n_in,
                              void* d_out, int out_size) {
    const float* x    = (const float*)d_in[0];
    const float* bias = (const float*)d_in[1];
    const float* W_P  = (const float*)d_in[2];
    const float* b_P  = (const float*)d_in[3];
    const float* Wpos = (const float*)d_in[4];
    const float* Wq   = (const float*)d_in[5];
    const float* bq   = (const float*)d_in[6];
    const float* Wk   = (const float*)d_in[7];
    const float* bk   = (const float*)d_in[8];
    const float* Wv   = (const float*)d_in[9];
    const float* bv   = (const float*)d_in[10];
    const float* Wo   = (const float*)d_in[11];
    const float* bo   = (const float*)d_in[12];
    const float* g1   = (const float*)d_in[13];
    const float* be1  = (const float*)d_in[14];
    const float* W1   = (const float*)d_in[15];
    const float* b1   = (const float*)d_in[16];
    const float* W2   = (const float*)d_in[17];
    const float* b2   = (const float*)d_in[18];
    const float* g2   = (const float*)d_in[19];
    const float* be2  = (const float*)d_in[20];
    float* out = (float*)d_out;

    float *z,*qb,*kb,*vb,*ob,*tb,*fb,*sc;
    cudaGetSymbolAddress((void**)&z,  g_z);
    cudaGetSymbolAddress((void**)&qb, g_q);
    cudaGetSymbolAddress((void**)&kb, g_k);
    cudaGetSymbolAddress((void**)&vb, g_v);
    cudaGetSymbolAddress((void**)&ob, g_o);
    cudaGetSymbolAddress((void**)&tb, g_t);
    cudaGetSymbolAddress((void**)&fb, g_f);
    cudaGetSymbolAddress((void**)&sc, g_sc);

    const int attnSmem = (2*Q_*DK_ + Q_*(Q_+1)) * (int)sizeof(float);  // 82432
    cudaFuncSetAttribute(attn_kernel, cudaFuncAttributeMaxDynamicSharedMemorySize, attnSmem);

    embed_kernel<<<MROWS, 256>>>(x, W_P, b_P, Wpos);

    dim3 gD(D_/64, MROWS/64);   // N=256
    dim3 gF(F_/64, MROWS/64);   // N=512

    for (int l = 0; l < 3; ++l) {
        const float* wq = Wq + (size_t)l*D_*D_;  const float* bq_ = bq + (size_t)l*D_;
        const float* wk = Wk + (size_t)l*D_*D_;  const float* bk_ = bk + (size_t)l*D_;
        const float* wv = Wv + (size_t)l*D_*D_;  const float* bv_ = bv + (size_t)l*D_;
        const float* wo = Wo + (size_t)l*D_*D_;  const float* bo_ = bo + (size_t)l*D_;
        const float* w1 = W1 + (size_t)l*D_*F_;  const float* b1_ = b1 + (size_t)l*F_;
        const float* w2 = W2 + (size_t)l*F_*D_;  const float* b2_ = b2 + (size_t)l*D_;
        const float* g1_ = g1 + (size_t)l*D_;    const float* be1_ = be1 + (size_t)l*D_;
        const float* g2_ = g2 + (size_t)l*D_;    const float* be2_ = be2 + (size_t)l*D_;

        gemm_kernel<0><<<gD, 256>>>(z, wq, bq_, qb, MROWS, D_, D_);
        gemm_kernel<0><<<gD, 256>>>(z, wk, bk_, kb, MROWS, D_, D_);
        gemm_kernel<0><<<gD, 256>>>(z, wv, bv_, vb, MROWS, D_, D_);

        attn_kernel<<<dim3(H_, B_), 128, attnSmem>>>(qb, kb, vb, bias, sc, ob,
                                                     (l > 0) ? 1 : 0, (l < 2) ? 1 : 0);

        gemm_kernel<0><<<gD, 256>>>(ob, wo, bo_, tb, MROWS, D_, D_);
        ln_kernel<<<MROWS, 256>>>(z, tb, g1_, be1_, z);

        gemm_kernel<1><<<gF, 256>>>(z, w1, b1_, fb, MROWS, F_, D_);
        gemm_kernel<0><<<gD, 256>>>(fb, w2, b2_, tb, MROWS, D_, F_);
        ln_kernel<<<MROWS, 256>>>(z, tb, g2_, be2_, (l == 2) ? out : z);
    }
}

// round 7
// speedup vs baseline: 1.2769x; 1.2769x over previous
#include <cuda_runtime.h>
#include <math.h>

#define B_ 256
#define Q_ 128
#define P_ 16
#define D_ 256
#define H_ 16
#define F_ 512
#define DK_ 16
#define MROWS (B_*Q_)        // 32768
#define SCALE_ 0.25f         // DK^-0.5
#define EPS_ 1e-5f

// ---- scratch (device globals: allocation-free) ----
__device__ float g_z [MROWS*D_];
__device__ float g_q [MROWS*D_];
__device__ float g_k [MROWS*D_];
__device__ float g_v [MROWS*D_];
__device__ float g_o [MROWS*D_];
__device__ float g_t [MROWS*D_];
__device__ float g_f [MROWS*F_];
__device__ float g_sc[(size_t)B_*H_*Q_*Q_];   // 268 MB score carry

// ---------------- embed: z = x @ W_P + b_P + W_pos ----------------
__global__ void embed_kernel(const float* __restrict__ x,
                             const float* __restrict__ W_P,
                             const float* __restrict__ b_P,
                             const float* __restrict__ W_pos) {
    int row = blockIdx.x;          // b*Q + q
    int d   = threadIdx.x;         // 0..255
    int q   = row % Q_;
    __shared__ float xs[P_];
    if (threadIdx.x < P_) xs[threadIdx.x] = x[row*P_ + threadIdx.x];
    __syncthreads();
    float acc = b_P[d] + W_pos[q*D_ + d];
#pragma unroll
    for (int p = 0; p < P_; ++p) acc += xs[p] * W_P[p*D_ + d];
    g_z[(size_t)row*D_ + d] = acc;
}

// ---------------- SGEMM: C = act(A[MxK] @ W[KxN] + bias) ----------------
// 128x128 tile, BK=16, 256 threads, 8x8 per thread, register prefetch.
// Requires M%128==0, N%128==0, K%16==0.
template<int ACT>
__global__ __launch_bounds__(256, 2)
void gemm_kernel(const float* __restrict__ A,
                 const float* __restrict__ W,
                 const float* __restrict__ bias,
                 float* __restrict__ C,
                 int M, int N, int K) {
    __shared__ float As[16][132];   // k-major, padded (132*4=528, 16B multiple)
    __shared__ float Bs[16][128];
    const int tid = threadIdx.x;
    const int m0 = blockIdx.y * 128, n0 = blockIdx.x * 128;
    const int aRow = tid >> 1,  aK = (tid & 1) << 3;   // each thread: 8 k of one A row
    const int bRow = tid >> 4,  bN = (tid & 15) << 3;  // each thread: 8 n of one W row
    const int tx = tid & 15,    ty = tid >> 4;

    const float* Ap = A + (size_t)(m0 + aRow)*K + aK;
    const float* Wp = W + (size_t)bRow*N + n0 + bN;

    float4 pa0 = *(const float4*)(Ap);
    float4 pa1 = *(const float4*)(Ap + 4);
    float4 pb0 = *(const float4*)(Wp);
    float4 pb1 = *(const float4*)(Wp + 4);

    float acc[8][8] = {};
    for (int k0 = 0; ; ) {
        __syncthreads();
        As[aK+0][aRow] = pa0.x; As[aK+1][aRow] = pa0.y;
        As[aK+2][aRow] = pa0.z; As[aK+3][aRow] = pa0.w;
        As[aK+4][aRow] = pa1.x; As[aK+5][aRow] = pa1.y;
        As[aK+6][aRow] = pa1.z; As[aK+7][aRow] = pa1.w;
        *(float4*)&Bs[bRow][bN]     = pb0;
        *(float4*)&Bs[bRow][bN + 4] = pb1;
        __syncthreads();
        k0 += 16;
        if (k0 < K) {   // prefetch next tile while computing this one
            pa0 = *(const float4*)(Ap + k0);
            pa1 = *(const float4*)(Ap + k0 + 4);
            pb0 = *(const float4*)(Wp + (size_t)k0*N);
            pb1 = *(const float4*)(Wp + (size_t)k0*N + 4);
        }
#pragma unroll
        for (int k = 0; k < 16; ++k) {
            float a_[8], b_[8];
            *(float4*)&a_[0] = *(const float4*)&As[k][ty*8];
            *(float4*)&a_[4] = *(const float4*)&As[k][ty*8 + 4];
            *(float4*)&b_[0] = *(const float4*)&Bs[k][tx*8];
            *(float4*)&b_[4] = *(const float4*)&Bs[k][tx*8 + 4];
#pragma unroll
            for (int i = 0; i < 8; ++i)
#pragma unroll
                for (int j = 0; j < 8; ++j) acc[i][j] += a_[i]*b_[j];
        }
        if (k0 >= K) break;
    }

    const int nb = n0 + tx*8;
    float bb[8];
    *(float4*)&bb[0] = *(const float4*)&bias[nb];
    *(float4*)&bb[4] = *(const float4*)&bias[nb + 4];
#pragma unroll
    for (int i = 0; i < 8; ++i) {
        int m = m0 + ty*8 + i;
        float r[8];
#pragma unroll
        for (int j = 0; j < 8; ++j) {
            float t = acc[i][j] + bb[j];
            if (ACT == 1) t = 0.5f*t*(1.0f + erff(t*0.70710678118654752f));
            r[j] = t;
        }
        *(float4*)&C[(size_t)m*N + nb]     = *(float4*)&r[0];
        *(float4*)&C[(size_t)m*N + nb + 4] = *(float4*)&r[4];
    }
}

// ---------------- fused attention per (b,h), coalesced score IO ----------------
__global__ void attn_kernel(const float* __restrict__ q,
                            const float* __restrict__ k,
                            const float* __restrict__ v,
                            const float* __restrict__ bias,
                            float* __restrict__ scores,
                            float* __restrict__ o,
                            int hasPrev, int writeScores) {
    const int h = blockIdx.x, b = blockIdx.y;
    const int tid = threadIdx.x;                  // 128 threads = query rows
    extern __shared__ float sm[];
    float* ks = sm;                               // 128*16
    float* vs = sm + Q_*DK_;                      // 128*16
    float* ss = sm + 2*Q_*DK_;                    // 128*(128+1)

    const size_t base  = ((size_t)b*Q_)*D_ + h*DK_;
    const size_t sbase = (((size_t)b*H_ + h)*Q_)*Q_;

    // K/V tiles
    for (int t = tid; t < Q_*DK_; t += 128) {
        int j = t >> 4, c = t & 15;
        ks[t] = k[base + (size_t)j*D_ + c];
        vs[t] = v[base + (size_t)j*D_ + c];
    }
    // Coalesced stage of bias (+prev scores) into ss. bias is (1,Q,Q): flat idx matches.
    if (hasPrev) {
        for (int idx = tid; idx < Q_*Q_; idx += 128) {
            ss[(idx >> 7)*(Q_+1) + (idx & 127)] = bias[idx] + scores[sbase + idx];
        }
    } else {
        for (int idx = tid; idx < Q_*Q_; idx += 128) {
            ss[(idx >> 7)*(Q_+1) + (idx & 127)] = bias[idx];
        }
    }
    float qr[DK_];
#pragma unroll
    for (int c = 0; c < DK_; ++c) qr[c] = q[base + (size_t)tid*D_ + c];
    __syncthreads();

    float* my = ss + tid*(Q_+1);
    float mx = -1e30f;
    for (int j = 0; j < Q_; ++j) {
        float dot = 0.f;
#pragma unroll
        for (int c = 0; c < DK_; ++c) dot += qr[c]*ks[j*DK_ + c];
        float s = dot*SCALE_ + my[j];
        my[j] = s;
        mx = fmaxf(mx, s);
    }

    if (writeScores) {   // uniform across block
        __syncthreads();
        for (int idx = tid; idx < Q_*Q_; idx += 128)
            scores[sbase + idx] = ss[(idx >> 7)*(Q_+1) + (idx & 127)];
        __syncthreads();
    }

    float sum = 0.f;
    for (int j = 0; j < Q_; ++j) { float e = __expf(my[j]-mx); my[j] = e; sum += e; }
    const float inv = 1.0f/sum;

    float oa[DK_] = {};
    for (int j = 0; j < Q_; ++j) {
        float p = my[j];
#pragma unroll
        for (int c = 0; c < DK_; ++c) oa[c] += p*vs[j*DK_ + c];
    }
#pragma unroll
    for (int c = 0; c < DK_; ++c) o[base + (size_t)tid*D_ + c] = oa[c]*inv;
}

// ---------------- fused residual + LayerNorm (one block per row, shuffle reduce) ----------------
__global__ void ln_kernel(const float* __restrict__ resid,
                          const float* __restrict__ add,
                          const float* __restrict__ g,
                          const float* __restrict__ bta,
                          float* __restrict__ out) {
    const int row = blockIdx.x, d = threadIdx.x;  // 256 threads
    __shared__ float w1s[8], w2s[8];
    float val = resid[(size_t)row*D_ + d] + add[(size_t)row*D_ + d];
    float s1 = val, s2 = val*val;
#pragma unroll
    for (int o = 16; o; o >>= 1) {
        s1 += __shfl_xor_sync(0xffffffffu, s1, o);
        s2 += __shfl_xor_sync(0xffffffffu, s2, o);
    }
    if ((d & 31) == 0) { w1s[d >> 5] = s1; w2s[d >> 5] = s2; }
    __syncthreads();
    float t1 = 0.f, t2 = 0.f;
#pragma unroll
    for (int i = 0; i < 8; ++i) { t1 += w1s[i]; t2 += w2s[i]; }
    float mu  = t1 * (1.0f/256.0f);
    float var = t2 * (1.0f/256.0f) - mu*mu;
    out[(size_t)row*D_ + d] = (val - mu) * rsqrtf(var + EPS_) * g[d] + bta[d];
}

// ---------------- launch ----------------
extern "C" void kernel_launch(void* const* d_in, const int* in_sizes, int n_in,
                              void* d_out, int out_size) {
    const float* x    = (const float*)d_in[0];
    const float* bias = (const float*)d_in[1];
    const float* W_P  = (const float*)d_in[2];
    const float* b_P  = (const float*)d_in[3];
    const float* Wpos = (const float*)d_in[4];
    const float* Wq   = (const float*)d_in[5];
    const float* bq   = (const float*)d_in[6];
    const float* Wk   = (const float*)d_in[7];
    const float* bk   = (const float*)d_in[8];
    const float* Wv   = (const float*)d_in[9];
    const float* bv   = (const float*)d_in[10];
    const float* Wo   = (const float*)d_in[11];
    const float* bo   = (const float*)d_in[12];
    const float* g1   = (const float*)d_in[13];
    const float* be1  = (const float*)d_in[14];
    const float* W1   = (const float*)d_in[15];
    const float* b1   = (const float*)d_in[16];
    const float* W2   = (const float*)d_in[17];
    const float* b2   = (const float*)d_in[18];
    const float* g2   = (const float*)d_in[19];
    const float* be2  = (const float*)d_in[20];
    float* out = (float*)d_out;

    float *z,*qb,*kb,*vb,*ob,*tb,*fb,*sc;
    cudaGetSymbolAddress((void**)&z,  g_z);
    cudaGetSymbolAddress((void**)&qb, g_q);
    cudaGetSymbolAddress((void**)&kb, g_k);
    cudaGetSymbolAddress((void**)&vb, g_v);
    cudaGetSymbolAddress((void**)&ob, g_o);
    cudaGetSymbolAddress((void**)&tb, g_t);
    cudaGetSymbolAddress((void**)&fb, g_f);
    cudaGetSymbolAddress((void**)&sc, g_sc);

    const int attnSmem = (2*Q_*DK_ + Q_*(Q_+1)) * (int)sizeof(float);  // 82432
    cudaFuncSetAttribute(attn_kernel, cudaFuncAttributeMaxDynamicSharedMemorySize, attnSmem);

    embed_kernel<<<MROWS, 256>>>(x, W_P, b_P, Wpos);

    dim3 gD(D_/128, MROWS/128);   // (2, 256)
    dim3 gF(F_/128, MROWS/128);   // (4, 256)

    for (int l = 0; l < 3; ++l) {
        const float* wq = Wq + (size_t)l*D_*D_;  const float* bq_ = bq + (size_t)l*D_;
        const float* wk = Wk + (size_t)l*D_*D_;  const float* bk_ = bk + (size_t)l*D_;
        const float* wv = Wv + (size_t)l*D_*D_;  const float* bv_ = bv + (size_t)l*D_;
        const float* wo = Wo + (size_t)l*D_*D_;  const float* bo_ = bo + (size_t)l*D_;
        const float* w1 = W1 + (size_t)l*D_*F_;  const float* b1_ = b1 + (size_t)l*F_;
        const float* w2 = W2 + (size_t)l*F_*D_;  const float* b2_ = b2 + (size_t)l*D_;
        const float* g1_ = g1 + (size_t)l*D_;    const float* be1_ = be1 + (size_t)l*D_;
        const float* g2_ = g2 + (size_t)l*D_;    const float* be2_ = be2 + (size_t)l*D_;

        gemm_kernel<0><<<gD, 256>>>(z, wq, bq_, qb, MROWS, D_, D_);
        gemm_kernel<0><<<gD, 256>>>(z, wk, bk_, kb, MROWS, D_, D_);
        gemm_kernel<0><<<gD, 256>>>(z, wv, bv_, vb, MROWS, D_, D_);

        attn_kernel<<<dim3(H_, B_), 128, attnSmem>>>(qb, kb, vb, bias, sc, ob,
                                                     (l > 0) ? 1 : 0, (l < 2) ? 1 : 0);

        gemm_kernel<0><<<gD, 256>>>(ob, wo, bo_, tb, MROWS, D_, D_);
        ln_kernel<<<MROWS, 256>>>(z, tb, g1_, be1_, z);

        gemm_kernel<1><<<gF, 256>>>(z, w1, b1_, fb, MROWS, F_, D_);
        gemm_kernel<0><<<gD, 256>>>(fb, w2, b2_, tb, MROWS, D_, F_);
        ln_kernel<<<MROWS, 256>>>(z, tb, g2_, be2_, (l == 2) ? out : z);
    }
}